// round 1
// baseline (speedup 1.0000x reference)
#include <cuda_runtime.h>
#include <cuda_bf16.h>

#define N_NODES 50000
#define E_EDGES 1600000

// ---------------- scratch (device globals; no allocation allowed) ----------------
__device__ float g_agg1[N_NODES * 64];   // sum of x[src] per dst
__device__ float g_h1  [N_NODES * 64];   // relu(layer1) output
__device__ float g_y2  [N_NODES * 32];   // h1 @ W2_l^T  (pre-aggregation, folded)
__device__ float g_r2  [N_NODES * 32];   // h1 @ W2_r^T  (self term, layer 2)
__device__ float g_agg2[N_NODES * 32];   // sum of y2[src] per dst
__device__ float g_deg [N_NODES];        // in-degree (float)
__device__ int   g_is64;                 // edge_index dtype flag

// ---------------- dtype detection (int64 vs int32 edge_index) ----------------
__global__ void detect_dtype_k(const long long* __restrict__ ei) {
    if (threadIdx.x == 0 && blockIdx.x == 0) {
        int ok = 1;
        for (int i = 0; i < 64; i++) {
            long long v = ei[i];
            if (v < 0 || v >= N_NODES) { ok = 0; break; }
        }
        g_is64 = ok;
    }
}

// ---------------- zero accumulators ----------------
__global__ void zero_k() {
    int idx = blockIdx.x * blockDim.x + threadIdx.x;
    int stride = gridDim.x * blockDim.x;
    for (int i = idx; i < N_NODES * 64; i += stride) g_agg1[i] = 0.0f;
    for (int i = idx; i < N_NODES * 32; i += stride) g_agg2[i] = 0.0f;
    for (int i = idx; i < N_NODES;      i += stride) g_deg[i]  = 0.0f;
}

__device__ __forceinline__ void red_add_v4(float* p, float4 v) {
    asm volatile("red.global.add.v4.f32 [%0], {%1, %2, %3, %4};"
                 :: "l"(p), "f"(v.x), "f"(v.y), "f"(v.z), "f"(v.w) : "memory");
}

__device__ __forceinline__ void load_edge(const void* ei, int e, int& src, int& dst) {
    if (g_is64) {
        const long long* p = (const long long*)ei;
        src = (int)__ldg(&p[e]);
        dst = (int)__ldg(&p[E_EDGES + e]);
    } else {
        const int* p = (const int*)ei;
        src = __ldg(&p[e]);
        dst = __ldg(&p[E_EDGES + e]);
    }
}

// ---------------- scatter layer 1: agg1[dst] += x[src]  (64 ch), deg ----------------
// one thread per (edge, 16B chunk): E * 16 threads
__global__ void scatter1_k(const float* __restrict__ x, const void* __restrict__ ei) {
    int idx = blockIdx.x * blockDim.x + threadIdx.x;
    if (idx >= E_EDGES * 16) return;
    int e = idx >> 4;
    int c = idx & 15;
    int src, dst;
    load_edge(ei, e, src, dst);
    float4 v = __ldg((const float4*)(x + (size_t)src * 64 + c * 4));
    red_add_v4(g_agg1 + (size_t)dst * 64 + c * 4, v);
    if (c == 0) atomicAdd(&g_deg[dst], 1.0f);
}

// ---------------- layer 1 dense epilogue ----------------
// h1 = relu(agg1/deg @ W1_l^T + b1 + x @ W1_r^T)
// 256 threads, 4 nodes per iter (64 threads/node, 1 output ch/thread).
// Weights in smem as interleaved transposed pairs: Wc[k*64+o] = {W1_l[o][k], W1_r[o][k]}.
__global__ void layer1_k(const float* __restrict__ x,
                         const float* __restrict__ W1l, const float* __restrict__ b1,
                         const float* __restrict__ W1r) {
    __shared__ float2 Wc[64 * 64];
    __shared__ float2 ax[4][64];   // {agg_mean, x}
    __shared__ float  b1s[64];

    int tid = threadIdx.x;
    for (int i = tid; i < 64 * 64; i += 256) {
        int k = i >> 6, o = i & 63;
        Wc[i] = make_float2(W1l[o * 64 + k], W1r[o * 64 + k]);
    }
    if (tid < 64) b1s[tid] = b1[tid];
    __syncthreads();

    int g = tid >> 6;       // node slot 0..3
    int o = tid & 63;       // output channel

    for (int base = blockIdx.x * 4; base < N_NODES; base += gridDim.x * 4) {
        int node = base + g;
        __syncthreads();
        {
            float invd = 1.0f / fmaxf(g_deg[node], 1.0f);
            float a = g_agg1[(size_t)node * 64 + o] * invd;
            float xv = __ldg(&x[(size_t)node * 64 + o]);
            ax[g][o] = make_float2(a, xv);
        }
        __syncthreads();

        float acc = b1s[o];
        #pragma unroll
        for (int k = 0; k < 64; k++) {
            float2 w = Wc[k * 64 + o];
            float2 v = ax[g][k];
            acc = fmaf(v.x, w.x, acc);
            acc = fmaf(v.y, w.y, acc);
        }
        g_h1[(size_t)node * 64 + o] = fmaxf(acc, 0.0f);
    }
}

// ---------------- layer 2 pre-projection (folds W2_l through the aggregation) ----------------
// y2 = h1 @ W2_l^T ; r2 = h1 @ W2_r^T
// 256 threads, 8 nodes per iter (32 threads/node, each computes one y2 and one r2 channel).
__global__ void layer2pre_k(const float* __restrict__ W2l, const float* __restrict__ W2r) {
    __shared__ float2 Wc[64 * 32];  // Wc[k*32+o] = {W2_l[o][k], W2_r[o][k]}
    __shared__ float  hs[8][64];

    int tid = threadIdx.x;
    for (int i = tid; i < 64 * 32; i += 256) {
        int k = i >> 5, o = i & 31;
        Wc[i] = make_float2(W2l[o * 64 + k], W2r[o * 64 + k]);
    }
    __syncthreads();

    int g = tid >> 5;       // node slot 0..7
    int o = tid & 31;       // output channel

    for (int base = blockIdx.x * 8; base < N_NODES; base += gridDim.x * 8) {
        __syncthreads();
        // stage 8 rows of h1 (512 floats, 2 per thread)
        #pragma unroll
        for (int i = tid; i < 512; i += 256) {
            int j = i >> 6, k = i & 63;
            hs[j][k] = g_h1[(size_t)(base + j) * 64 + k];
        }
        __syncthreads();

        float y = 0.0f, r = 0.0f;
        #pragma unroll
        for (int k = 0; k < 64; k++) {
            float2 w = Wc[k * 32 + o];
            float hk = hs[g][k];
            y = fmaf(hk, w.x, y);
            r = fmaf(hk, w.y, r);
        }
        int node = base + g;
        g_y2[(size_t)node * 32 + o] = y;
        g_r2[(size_t)node * 32 + o] = r;
    }
}

// ---------------- scatter layer 2: agg2[dst] += y2[src] (32 ch) ----------------
// one thread per (edge, 16B chunk): E * 8 threads
__global__ void scatter2_k(const void* __restrict__ ei) {
    int idx = blockIdx.x * blockDim.x + threadIdx.x;
    if (idx >= E_EDGES * 8) return;
    int e = idx >> 3;
    int c = idx & 7;
    int src, dst;
    load_edge(ei, e, src, dst);
    float4 v = __ldg((const float4*)(g_y2 + (size_t)src * 32 + c * 4));
    red_add_v4(g_agg2 + (size_t)dst * 32 + c * 4, v);
}

// ---------------- final: h2 = relu(agg2/deg + b2 + r2); out = h2 @ W_lin^T + b_lin ----------------
// one warp per node; lane = channel; warp-reduce the dot with W_lin.
__global__ void final_k(const float* __restrict__ b2, const float* __restrict__ Wlin,
                        const float* __restrict__ blin, float* __restrict__ out) {
    int warp = (blockIdx.x * blockDim.x + threadIdx.x) >> 5;
    int lane = threadIdx.x & 31;
    if (warp >= N_NODES) return;
    float invd = 1.0f / fmaxf(g_deg[warp], 1.0f);
    float v = g_agg2[(size_t)warp * 32 + lane] * invd + __ldg(&b2[lane])
            + g_r2[(size_t)warp * 32 + lane];
    v = fmaxf(v, 0.0f) * __ldg(&Wlin[lane]);
    #pragma unroll
    for (int s = 16; s; s >>= 1) v += __shfl_xor_sync(0xFFFFFFFFu, v, s);
    if (lane == 0) out[warp] = v + __ldg(&blin[0]);
}

// ---------------- launch ----------------
extern "C" void kernel_launch(void* const* d_in, const int* in_sizes, int n_in,
                              void* d_out, int out_size) {
    const float* x    = (const float*)d_in[0];
    const void*  ei   = d_in[1];
    const float* W1l  = (const float*)d_in[2];
    const float* b1   = (const float*)d_in[3];
    const float* W1r  = (const float*)d_in[4];
    const float* W2l  = (const float*)d_in[5];
    const float* b2   = (const float*)d_in[6];
    const float* W2r  = (const float*)d_in[7];
    const float* Wlin = (const float*)d_in[8];
    const float* blin = (const float*)d_in[9];
    float* out = (float*)d_out;

    detect_dtype_k<<<1, 1>>>((const long long*)ei);
    zero_k<<<4096, 256>>>();
    scatter1_k<<<(E_EDGES * 16) / 256, 256>>>(x, ei);
    layer1_k<<<592, 256>>>(x, W1l, b1, W1r);
    layer2pre_k<<<592, 256>>>(W2l, W2r);
    scatter2_k<<<(E_EDGES * 8) / 256, 256>>>(ei);
    final_k<<<(N_NODES * 32 + 255) / 256, 256>>>(b2, Wlin, blin, out);
}